// round 7
// baseline (speedup 1.0000x reference)
#include <cuda_runtime.h>
#include <cstdint>

#define HH 264
#define WW 264
#define HWP (HH*WW)      // 69696
#define C 96
#define C3 288
#define SHIFT 4

typedef unsigned long long ull;

// ---- scratch (static device globals; allocation is forbidden) ----
__device__ float g_qkv[C3 * HWP];        // after 1x1 conv (shifted frame)
__device__ float g_dw [C3 * HWP];        // after depthwise 3x3
__device__ float g_out[25 * C * 4096];   // per-tile attention output
__device__ float g_pred[C * HWP];        // merged/averaged attention output
__device__ float g_wT [C * C3];          // qkv_w transposed [k][oc]
__device__ float g_pwT[C * C];           // proj_w transposed [k][oc]

__constant__ int c_off[5] = {0, 50, 100, 150, 200};

// ---- packed fp32x2 helpers (Blackwell FFMA2: PTX-only) ----
__device__ __forceinline__ ull pack2(float x) {
    unsigned int u = __float_as_uint(x);
    ull r;
    asm("mov.b64 %0, {%1, %1};" : "=l"(r) : "r"(u));
    return r;
}
__device__ __forceinline__ void fma2(ull& d, ull a, ull b) {
    asm("fma.rn.f32x2 %0, %1, %2, %0;" : "+l"(d) : "l"(a), "l"(b));
}
__device__ __forceinline__ float2 unpack2(ull v) {
    unsigned int lo, hi;
    asm("mov.b64 {%0, %1}, %2;" : "=r"(lo), "=r"(hi) : "l"(v));
    return make_float2(__uint_as_float(lo), __uint_as_float(hi));
}
__device__ __forceinline__ float4 cat2(ull a, ull b) {
    float2 x = unpack2(a), y = unpack2(b);
    return make_float4(x.x, x.y, y.x, y.y);
}

// --------------------------------------------------------------------------
// K0: transpose the two weight matrices once (tiny)
// --------------------------------------------------------------------------
__global__ void transpose_w_kernel(const float* __restrict__ qkvw,
                                   const float* __restrict__ pw)
{
    int i = blockIdx.x * 256 + threadIdx.x;
    if (i < C3 * C) { int oc = i / C, k = i % C; g_wT [k * C3 + oc] = qkvw[i]; }
    if (i < C  * C) { int oc = i / C, k = i % C; g_pwT[k * C  + oc] = pw[i]; }
}

// --------------------------------------------------------------------------
// K1: qkv = qkv_w @ x_shifted. M=96 (per blockIdx.y), N=128 px, K=96.
// 192 threads = 12 oc-groups(8 oc) x 16 px-groups(8 px). f32x2 accumulators.
// Register-prefetch pipeline: next K-chunk LDGs overlap current compute.
// --------------------------------------------------------------------------
#define KC 16
#define PFN 11    // ceil(KC*128 / 192)
__global__ __launch_bounds__(192) void qkv_gemm_kernel(const float* __restrict__ x)
{
    __shared__ float sWT[C * C];       // [k][oc] stride 96
    __shared__ float sX[KC * 128];
    __shared__ int   s_src[128];

    const int tid = threadIdx.x;
    const int p0  = blockIdx.x * 128;
    const int oc0 = blockIdx.y * C;

    if (tid < 128) {
        int p = p0 + tid; if (p >= HWP) p = HWP - 1;
        int h = p / WW, ww = p % WW;
        int hs = h + SHIFT; if (hs >= HH) hs -= HH;
        int ws = ww + SHIFT; if (ws >= WW) ws -= WW;
        s_src[tid] = hs * WW + ws;
    }
    for (int i = tid; i < C * C; i += 192) {
        int k = i / C, oc = i % C;
        sWT[k * C + oc] = g_wT[k * C3 + oc0 + oc];
    }
    __syncthreads();   // s_src ready for prefetch

    const int og = tid / 16, pg = tid % 16;
    ull acc[8][4] = {};
    float pf[PFN];

    #pragma unroll
    for (int j = 0; j < PFN; j++) {
        int idx = tid + j * 192;
        if (idx < KC * 128)
            pf[j] = x[((idx >> 7)) * HWP + s_src[idx & 127]];
    }

    for (int kc = 0; kc < C / KC; kc++) {
        __syncthreads();
        #pragma unroll
        for (int j = 0; j < PFN; j++) {
            int idx = tid + j * 192;
            if (idx < KC * 128) sX[idx] = pf[j];
        }
        __syncthreads();
        if (kc + 1 < C / KC) {
            #pragma unroll
            for (int j = 0; j < PFN; j++) {
                int idx = tid + j * 192;
                if (idx < KC * 128)
                    pf[j] = x[((kc + 1) * KC + (idx >> 7)) * HWP + s_src[idx & 127]];
            }
        }
        #pragma unroll
        for (int k = 0; k < KC; k++) {
            float4 wa = *(const float4*)&sWT[(kc * KC + k) * C + og * 8];
            float4 wb = *(const float4*)&sWT[(kc * KC + k) * C + og * 8 + 4];
            ull wp[8];
            wp[0] = pack2(wa.x); wp[1] = pack2(wa.y);
            wp[2] = pack2(wa.z); wp[3] = pack2(wa.w);
            wp[4] = pack2(wb.x); wp[5] = pack2(wb.y);
            wp[6] = pack2(wb.z); wp[7] = pack2(wb.w);
            ulonglong2 xa = *(const ulonglong2*)&sX[k * 128 + pg * 8];
            ulonglong2 xb = *(const ulonglong2*)&sX[k * 128 + pg * 8 + 4];
            #pragma unroll
            for (int o = 0; o < 8; o++) {
                fma2(acc[o][0], wp[o], xa.x);
                fma2(acc[o][1], wp[o], xa.y);
                fma2(acc[o][2], wp[o], xb.x);
                fma2(acc[o][3], wp[o], xb.y);
            }
        }
    }
    if (p0 + pg * 8 < HWP) {
        #pragma unroll
        for (int o = 0; o < 8; o++) {
            float* dst = &g_qkv[(oc0 + og * 8 + o) * HWP + p0 + pg * 8];
            *(float4*)dst       = cat2(acc[o][0], acc[o][1]);
            *(float4*)(dst + 4) = cat2(acc[o][2], acc[o][3]);
        }
    }
}

// --------------------------------------------------------------------------
// K2: depthwise 3x3, pad 1, 288 channels, 2 rows x 8 px per thread.
// 4 input rows serve 2 output rows (row reuse cuts L1 traffic ~33%).
// --------------------------------------------------------------------------
#define DWG ((HH/2) * 33)   // 4356 groups per channel
__global__ __launch_bounds__(256) void dwconv_kernel(const float* __restrict__ dww)
{
    const int c = blockIdx.y;
    const int g = blockIdx.x * 256 + threadIdx.x;
    if (g >= DWG) return;
    const int h0 = (g / 33) * 2;
    const int w0 = (g % 33) * 8;
    const float* in = g_qkv + c * HWP;

    float wt[9];
    #pragma unroll
    for (int i = 0; i < 9; i++) wt[i] = __ldg(&dww[c * 9 + i]);

    float v[4][10];
    #pragma unroll
    for (int r = 0; r < 4; r++) {
        int y = h0 + r - 1;
        if ((unsigned)y >= HH) {
            #pragma unroll
            for (int j = 0; j < 10; j++) v[r][j] = 0.f;
        } else {
            const float* b = in + y * WW + w0;
            float4 A = *(const float4*)b;
            float4 B = *(const float4*)(b + 4);
            v[r][0] = (w0 > 0) ? __ldg(b - 1) : 0.f;
            v[r][1] = A.x; v[r][2] = A.y; v[r][3] = A.z; v[r][4] = A.w;
            v[r][5] = B.x; v[r][6] = B.y; v[r][7] = B.z; v[r][8] = B.w;
            v[r][9] = (w0 + 8 < WW) ? __ldg(b + 8) : 0.f;
        }
    }
    #pragma unroll
    for (int orow = 0; orow < 2; orow++) {
        float o[8] = {};
        #pragma unroll
        for (int ky = 0; ky < 3; ky++) {
            #pragma unroll
            for (int kx = 0; kx < 3; kx++) {
                float wv = wt[ky * 3 + kx];
                #pragma unroll
                for (int pp = 0; pp < 8; pp++) o[pp] += wv * v[orow + ky][kx + pp];
            }
        }
        float* dst = g_dw + c * HWP + (h0 + orow) * WW + w0;
        *(float4*)dst       = make_float4(o[0], o[1], o[2], o[3]);
        *(float4*)(dst + 4) = make_float4(o[4], o[5], o[6], o[7]);
    }
}

// --------------------------------------------------------------------------
// K3: per-(window,head) channel attention. grid (1600,3), 64 threads.
// R5 form (AV reads v directly from g_dw); launch_bounds(64,12).
// --------------------------------------------------------------------------
__global__ __launch_bounds__(64, 12) void attn_kernel(const float* __restrict__ temp)
{
    __shared__ float s_q[32 * 68];   // swizzled; reused as s_g (32*36) after gram
    __shared__ float s_k[32 * 68];   // swizzled
    __shared__ float s_qn[32], s_kn[32];

    const int tid  = threadIdx.x;
    const int win  = blockIdx.x;
    const int head = blockIdx.y;
    const int t    = win >> 6;
    const int w64  = win & 63;
    const int wy = w64 >> 3, wx = w64 & 7;
    const int r0  = c_off[t / 5] + wy * 8;
    const int cc0 = c_off[t % 5] + wx * 8;

    // load q,k (64 ch x 64 px) as float2 with additive chunk swizzle
    for (int i = tid; i < 64 * 32; i += 64) {
        int ch = i >> 5, pr = i & 31;
        int r = pr >> 2, j = (pr & 3) * 2;
        int gch = (ch < 32) ? head * 32 + ch : 96 + head * 32 + (ch - 32);
        float2 v = *(const float2*)&g_dw[gch * HWP + (r0 + r) * WW + cc0 + j];
        int n = r * 8 + j;
        int row = ch & 31;
        float* dst = (ch < 32) ? s_q : s_k;
        int phys = (((n >> 2) + (row >> 2)) & 15) * 4 + (n & 3);
        *(float2*)&dst[row * 68 + phys] = v;
    }
    __syncthreads();

    // inverse L2 norms (order-agnostic: physical layout is a permutation)
    {
        const float* row = (tid < 32) ? (s_q + tid * 68) : (s_k + (tid - 32) * 68);
        float s = 0.f;
        #pragma unroll
        for (int cch = 0; cch < 16; cch++) {
            float4 v = *(const float4*)&row[cch * 4];
            s += v.x * v.x + v.y * v.y + v.z * v.z + v.w * v.w;
        }
        float inv = 1.0f / fmaxf(sqrtf(s), 1e-12f);
        if (tid < 32) s_qn[tid] = inv; else s_kn[tid - 32] = inv;
    }
    __syncthreads();

    // gram: 4x4 block per thread (8 qg x 8 kg), K=64 via f32x2
    const int qg = tid >> 3, kg = tid & 7;
    const int qr = qg * 4, kr = kg * 4;
    float gv[4][4];
    {
        ull acc[4][4] = {};
        #pragma unroll 4
        for (int lc = 0; lc < 16; lc++) {
            int qp = ((lc + qg) & 15) * 4;
            int kp = ((lc + kg) & 15) * 4;
            ulonglong2 qa[4], kb[4];
            #pragma unroll
            for (int i = 0; i < 4; i++)
                qa[i] = *(const ulonglong2*)&s_q[(qr + i) * 68 + qp];
            #pragma unroll
            for (int j = 0; j < 4; j++)
                kb[j] = *(const ulonglong2*)&s_k[(kr + j) * 68 + kp];
            #pragma unroll
            for (int i = 0; i < 4; i++)
                #pragma unroll
                for (int j = 0; j < 4; j++) {
                    fma2(acc[i][j], qa[i].x, kb[j].x);
                    fma2(acc[i][j], qa[i].y, kb[j].y);
                }
        }
        const float tmp = __ldg(&temp[head]);
        #pragma unroll
        for (int i = 0; i < 4; i++)
            #pragma unroll
            for (int j = 0; j < 4; j++) {
                float2 pr = unpack2(acc[i][j]);
                gv[i][j] = fmaxf((pr.x + pr.y) * s_qn[qr + i] * s_kn[kr + j] * tmp, 0.f);
            }
    }
    __syncthreads();
    float* s_g = s_q;                // overlay: G^T as s_g[d][c], stride 36
    #pragma unroll
    for (int j = 0; j < 4; j++)
        *(float4*)&s_g[(kr + j) * 36 + qr] =
            make_float4(gv[0][j], gv[1][j], gv[2][j], gv[3][j]);
    __syncthreads();

    // AV: out[c][n] = sum_d G[c][d] v[d][n]; v straight from g_dw (8B loads)
    {
        const int cog = tid >> 3, pxg = tid & 7;
        const int co = cog * 4;
        const float* vbase = g_dw + (size_t)(192 + head * 32) * HWP
                           + (r0 + pxg) * WW + cc0;
        ull av[4][4] = {};
        #pragma unroll 4
        for (int d = 0; d < 32; d++) {
            float4 g4 = *(const float4*)&s_g[d * 36 + co];
            ull gp[4] = {pack2(g4.x), pack2(g4.y), pack2(g4.z), pack2(g4.w)};
            const ull* vr = (const ull*)(vbase + (size_t)d * HWP);
            ull v0 = vr[0], v1 = vr[1], v2 = vr[2], v3 = vr[3];
            #pragma unroll
            for (int i = 0; i < 4; i++) {
                fma2(av[i][0], gp[i], v0);
                fma2(av[i][1], gp[i], v1);
                fma2(av[i][2], gp[i], v2);
                fma2(av[i][3], gp[i], v3);
            }
        }
        float* base = g_out + (t * 96 + head * 32 + co) * 4096
                    + (wy * 8 + pxg) * 64 + wx * 8;
        #pragma unroll
        for (int i = 0; i < 4; i++) {
            *(float4*)(base + i * 4096)     = cat2(av[i][0], av[i][1]);
            *(float4*)(base + i * 4096 + 4) = cat2(av[i][2], av[i][3]);
        }
    }
}

// --------------------------------------------------------------------------
// K3b: merge overlapping tiles into g_pred (averaged). One thread per pixel,
// offsets computed once and amortized over all 96 channels.
// --------------------------------------------------------------------------
__global__ __launch_bounds__(256) void merge_kernel()
{
    const int p = blockIdx.x * 256 + threadIdx.x;
    if (p >= HWP) return;
    const int h = p / WW, ww = p % WW;

    int toff[4]; int nt = 0;
    int rt[2], ct[2], nr = 0, nc = 0;
    #pragma unroll
    for (int o = 0; o < 5; o++) {
        int off = c_off[o];
        if (off <= h  && h  < off + 64) rt[nr++] = o;
        if (off <= ww && ww < off + 64) ct[nc++] = o;
    }
    for (int a = 0; a < nr; a++)
        for (int b = 0; b < nc; b++) {
            int tt = rt[a] * 5 + ct[b];
            toff[nt++] = tt * (96 * 4096)
                + (h - c_off[rt[a]]) * 64 + (ww - c_off[ct[b]]);
        }
    const float icnt = 1.0f / (float)nt;

    if (nt == 1) {
        const float* src = g_out + toff[0];
        for (int c = 0; c < C; c++)
            g_pred[c * HWP + p] = src[c * 4096];
    } else {
        for (int c = 0; c < C; c++) {
            float s = 0.f;
            for (int m = 0; m < nt; m++) s += g_out[toff[m] + c * 4096];
            g_pred[c * HWP + p] = s * icnt;
        }
    }
}

// --------------------------------------------------------------------------
// K4: out = proj_w @ g_pred, prefetch-pipelined GEMM (same scheme as K1),
// (+4,+4) unshift folded into the store mapping.
// --------------------------------------------------------------------------
__global__ __launch_bounds__(192) void proj_gemm_kernel(float* __restrict__ out)
{
    __shared__ float sWT[C * C];
    __shared__ float sX[KC * 128];
    __shared__ int   s_dst[128];

    const int tid = threadIdx.x;
    const int p0  = blockIdx.x * 128;

    if (tid < 128) {
        int p = p0 + tid; if (p >= HWP) p = HWP - 1;
        int h = p / WW, ww = p % WW;
        int hd = h + SHIFT; if (hd >= HH) hd -= HH;
        int wd = ww + SHIFT; if (wd >= WW) wd -= WW;
        s_dst[tid] = hd * WW + wd;
    }
    for (int i = tid; i < C * C; i += 192) sWT[i] = g_pwT[i];
    __syncthreads();

    const int og = tid / 16, pg = tid % 16;
    ull acc[8][4] = {};
    float pf[PFN];

    #pragma unroll
    for (int j = 0; j < PFN; j++) {
        int idx = tid + j * 192;
        if (idx < KC * 128) {
            int px = p0 + (idx & 127); if (px >= HWP) px = HWP - 1;
            pf[j] = g_pred[(idx >> 7) * HWP + px];
        }
    }

    for (int kc = 0; kc < C / KC; kc++) {
        __syncthreads();
        #pragma unroll
        for (int j = 0; j < PFN; j++) {
            int idx = tid + j * 192;
            if (idx < KC * 128) sX[idx] = pf[j];
        }
        __syncthreads();
        if (kc + 1 < C / KC) {
            #pragma unroll
            for (int j = 0; j < PFN; j++) {
                int idx = tid + j * 192;
                if (idx < KC * 128) {
                    int px = p0 + (idx & 127); if (px >= HWP) px = HWP - 1;
                    pf[j] = g_pred[((kc + 1) * KC + (idx >> 7)) * HWP + px];
                }
            }
        }
        #pragma unroll
        for (int k = 0; k < KC; k++) {
            float4 wa = *(const float4*)&sWT[(kc * KC + k) * C + og * 8];
            float4 wb = *(const float4*)&sWT[(kc * KC + k) * C + og * 8 + 4];
            ull wp[8];
            wp[0] = pack2(wa.x); wp[1] = pack2(wa.y);
            wp[2] = pack2(wa.z); wp[3] = pack2(wa.w);
            wp[4] = pack2(wb.x); wp[5] = pack2(wb.y);
            wp[6] = pack2(wb.z); wp[7] = pack2(wb.w);
            ulonglong2 xa = *(const ulonglong2*)&sX[k * 128 + pg * 8];
            ulonglong2 xb = *(const ulonglong2*)&sX[k * 128 + pg * 8 + 4];
            #pragma unroll
            for (int o = 0; o < 8; o++) {
                fma2(acc[o][0], wp[o], xa.x);
                fma2(acc[o][1], wp[o], xa.y);
                fma2(acc[o][2], wp[o], xb.x);
                fma2(acc[o][3], wp[o], xb.y);
            }
        }
    }
    if (p0 + pg * 8 < HWP) {
        #pragma unroll
        for (int o = 0; o < 8; o++) {
            const int oc = og * 8 + o;
            float4 v0 = cat2(acc[o][0], acc[o][1]);
            float4 v1 = cat2(acc[o][2], acc[o][3]);
            float vv[8] = {v0.x, v0.y, v0.z, v0.w, v1.x, v1.y, v1.z, v1.w};
            #pragma unroll
            for (int j = 0; j < 8; j++)
                out[oc * HWP + s_dst[pg * 8 + j]] = vv[j];
        }
    }
}

// --------------------------------------------------------------------------
extern "C" void kernel_launch(void* const* d_in, const int* in_sizes, int n_in,
                              void* d_out, int out_size)
{
    const float* x    = (const float*)d_in[0];   // (1,96,264,264)
    const float* temp = (const float*)d_in[1];   // (3,1,1)
    const float* qkvw = (const float*)d_in[2];   // (288,96)
    const float* dww  = (const float*)d_in[3];   // (288,1,3,3)
    const float* pw   = (const float*)d_in[4];   // (96,96)
    float* out = (float*)d_out;                  // (1,96,264,264)

    transpose_w_kernel<<<(C3 * C + 255) / 256, 256>>>(qkvw, pw);
    qkv_gemm_kernel<<<dim3((HWP + 127) / 128, 3), 192>>>(x);
    dwconv_kernel<<<dim3((DWG + 255) / 256, C3), 256>>>(dww);
    attn_kernel<<<dim3(1600, 3), 64>>>(temp);
    merge_kernel<<<(HWP + 255) / 256, 256>>>();
    proj_gemm_kernel<<<(HWP + 127) / 128, 192>>>(out);
}

// round 8
// speedup vs baseline: 1.1686x; 1.1686x over previous
#include <cuda_runtime.h>
#include <cstdint>

#define HH 264
#define WW 264
#define HWP (HH*WW)      // 69696
#define C 96
#define C3 288
#define SHIFT 4

typedef unsigned long long ull;

// ---- scratch (static device globals; allocation is forbidden) ----
__device__ float g_qkv[C3 * HWP];        // after 1x1 conv (shifted frame)
__device__ float g_dw [C3 * HWP];        // after depthwise 3x3
__device__ float g_out[25 * C * 4096];   // per-tile attention output
__device__ float g_wT [C * C3];          // qkv_w transposed [k][oc]
__device__ float g_pwT[C * C];           // proj_w transposed [k][oc]

__constant__ int c_off[5] = {0, 50, 100, 150, 200};

// ---- packed fp32x2 helpers (Blackwell FFMA2: PTX-only) ----
__device__ __forceinline__ ull pack2(float x) {
    unsigned int u = __float_as_uint(x);
    ull r;
    asm("mov.b64 %0, {%1, %1};" : "=l"(r) : "r"(u));
    return r;
}
__device__ __forceinline__ void fma2(ull& d, ull a, ull b) {
    asm("fma.rn.f32x2 %0, %1, %2, %0;" : "+l"(d) : "l"(a), "l"(b));
}
__device__ __forceinline__ float2 unpack2(ull v) {
    unsigned int lo, hi;
    asm("mov.b64 {%0, %1}, %2;" : "=r"(lo), "=r"(hi) : "l"(v));
    return make_float2(__uint_as_float(lo), __uint_as_float(hi));
}
__device__ __forceinline__ float4 cat2(ull a, ull b) {
    float2 x = unpack2(a), y = unpack2(b);
    return make_float4(x.x, x.y, y.x, y.y);
}

// --------------------------------------------------------------------------
// K0: transpose the two weight matrices once (tiny)
// --------------------------------------------------------------------------
__global__ void transpose_w_kernel(const float* __restrict__ qkvw,
                                   const float* __restrict__ pw)
{
    int i = blockIdx.x * 256 + threadIdx.x;
    if (i < C3 * C) { int oc = i / C, k = i % C; g_wT [k * C3 + oc] = qkvw[i]; }
    if (i < C  * C) { int oc = i / C, k = i % C; g_pwT[k * C  + oc] = pw[i]; }
}

// --------------------------------------------------------------------------
// K1: qkv = qkv_w @ x_shifted. M=96 (per blockIdx.y), N=128 px, K=96.
// 192 threads = 12 oc-groups(8 oc) x 16 px-groups(8 px). f32x2 accumulators.
// Register-prefetch pipeline: next K-chunk LDGs overlap current compute.
// --------------------------------------------------------------------------
#define KC 16
#define PFN 11    // ceil(KC*128 / 192)
__global__ __launch_bounds__(192) void qkv_gemm_kernel(const float* __restrict__ x)
{
    __shared__ float sWT[C * C];       // [k][oc] stride 96
    __shared__ float sX[KC * 128];
    __shared__ int   s_src[128];

    const int tid = threadIdx.x;
    const int p0  = blockIdx.x * 128;
    const int oc0 = blockIdx.y * C;

    if (tid < 128) {
        int p = p0 + tid; if (p >= HWP) p = HWP - 1;
        int h = p / WW, ww = p % WW;
        int hs = h + SHIFT; if (hs >= HH) hs -= HH;
        int ws = ww + SHIFT; if (ws >= WW) ws -= WW;
        s_src[tid] = hs * WW + ws;
    }
    for (int i = tid; i < C * C; i += 192) {
        int k = i / C, oc = i % C;
        sWT[k * C + oc] = g_wT[k * C3 + oc0 + oc];
    }
    __syncthreads();   // s_src ready for prefetch

    const int og = tid / 16, pg = tid % 16;
    ull acc[8][4] = {};
    float pf[PFN];

    #pragma unroll
    for (int j = 0; j < PFN; j++) {
        int idx = tid + j * 192;
        if (idx < KC * 128)
            pf[j] = x[((idx >> 7)) * HWP + s_src[idx & 127]];
    }

    for (int kc = 0; kc < C / KC; kc++) {
        __syncthreads();
        #pragma unroll
        for (int j = 0; j < PFN; j++) {
            int idx = tid + j * 192;
            if (idx < KC * 128) sX[idx] = pf[j];
        }
        __syncthreads();
        if (kc + 1 < C / KC) {
            #pragma unroll
            for (int j = 0; j < PFN; j++) {
                int idx = tid + j * 192;
                if (idx < KC * 128)
                    pf[j] = x[((kc + 1) * KC + (idx >> 7)) * HWP + s_src[idx & 127]];
            }
        }
        #pragma unroll
        for (int k = 0; k < KC; k++) {
            float4 wa = *(const float4*)&sWT[(kc * KC + k) * C + og * 8];
            float4 wb = *(const float4*)&sWT[(kc * KC + k) * C + og * 8 + 4];
            ull wp[8];
            wp[0] = pack2(wa.x); wp[1] = pack2(wa.y);
            wp[2] = pack2(wa.z); wp[3] = pack2(wa.w);
            wp[4] = pack2(wb.x); wp[5] = pack2(wb.y);
            wp[6] = pack2(wb.z); wp[7] = pack2(wb.w);
            ulonglong2 xa = *(const ulonglong2*)&sX[k * 128 + pg * 8];
            ulonglong2 xb = *(const ulonglong2*)&sX[k * 128 + pg * 8 + 4];
            #pragma unroll
            for (int o = 0; o < 8; o++) {
                fma2(acc[o][0], wp[o], xa.x);
                fma2(acc[o][1], wp[o], xa.y);
                fma2(acc[o][2], wp[o], xb.x);
                fma2(acc[o][3], wp[o], xb.y);
            }
        }
    }
    if (p0 + pg * 8 < HWP) {
        #pragma unroll
        for (int o = 0; o < 8; o++) {
            float* dst = &g_qkv[(oc0 + og * 8 + o) * HWP + p0 + pg * 8];
            *(float4*)dst       = cat2(acc[o][0], acc[o][1]);
            *(float4*)(dst + 4) = cat2(acc[o][2], acc[o][3]);
        }
    }
}

// --------------------------------------------------------------------------
// K2: depthwise 3x3, pad 1, 288 channels, 8 px per thread (264 = 33*8).
// (R6 form — the 2-row variant regressed.)
// --------------------------------------------------------------------------
__global__ __launch_bounds__(256) void dwconv_kernel(const float* __restrict__ dww)
{
    const int c = blockIdx.y;
    const int g = blockIdx.x * 256 + threadIdx.x;
    if (g >= HWP / 8) return;
    const int h  = g / 33;
    const int w0 = (g % 33) * 8;
    const float* in = g_qkv + c * HWP;

    float wt[9];
    #pragma unroll
    for (int i = 0; i < 9; i++) wt[i] = __ldg(&dww[c * 9 + i]);

    float o[8] = {};
    #pragma unroll
    for (int ky = 0; ky < 3; ky++) {
        int y = h + ky - 1;
        if ((unsigned)y >= HH) continue;
        const float* b = in + y * WW + w0;
        float4 A = *(const float4*)b;
        float4 B = *(const float4*)(b + 4);
        float L = (w0 > 0) ? __ldg(b - 1) : 0.f;
        float R = (w0 + 8 < WW) ? __ldg(b + 8) : 0.f;
        float v[10] = {L, A.x, A.y, A.z, A.w, B.x, B.y, B.z, B.w, R};
        #pragma unroll
        for (int kx = 0; kx < 3; kx++) {
            float wv = wt[ky * 3 + kx];
            #pragma unroll
            for (int pp = 0; pp < 8; pp++) o[pp] += wv * v[kx + pp];
        }
    }
    float* dst = g_dw + c * HWP + h * WW + w0;
    *(float4*)dst       = make_float4(o[0], o[1], o[2], o[3]);
    *(float4*)(dst + 4) = make_float4(o[4], o[5], o[6], o[7]);
}

// --------------------------------------------------------------------------
// K3: per-(window,head) channel attention. grid (1600,3), 64 threads.
// R5 form exactly: direct-LDG v in AV, launch_bounds(64,10) (regs ~94).
// --------------------------------------------------------------------------
__global__ __launch_bounds__(64, 10) void attn_kernel(const float* __restrict__ temp)
{
    __shared__ float s_q[32 * 68];   // swizzled; reused as s_g (32*36) after gram
    __shared__ float s_k[32 * 68];   // swizzled
    __shared__ float s_qn[32], s_kn[32];

    const int tid  = threadIdx.x;
    const int win  = blockIdx.x;
    const int head = blockIdx.y;
    const int t    = win >> 6;
    const int w64  = win & 63;
    const int wy = w64 >> 3, wx = w64 & 7;
    const int r0  = c_off[t / 5] + wy * 8;
    const int cc0 = c_off[t % 5] + wx * 8;

    // load q,k (64 ch x 64 px) as float2 with additive chunk swizzle
    for (int i = tid; i < 64 * 32; i += 64) {
        int ch = i >> 5, pr = i & 31;
        int r = pr >> 2, j = (pr & 3) * 2;
        int gch = (ch < 32) ? head * 32 + ch : 96 + head * 32 + (ch - 32);
        float2 v = *(const float2*)&g_dw[gch * HWP + (r0 + r) * WW + cc0 + j];
        int n = r * 8 + j;
        int row = ch & 31;
        float* dst = (ch < 32) ? s_q : s_k;
        int phys = (((n >> 2) + (row >> 2)) & 15) * 4 + (n & 3);
        *(float2*)&dst[row * 68 + phys] = v;
    }
    __syncthreads();

    // inverse L2 norms (order-agnostic: physical layout is a permutation)
    {
        const float* row = (tid < 32) ? (s_q + tid * 68) : (s_k + (tid - 32) * 68);
        float s = 0.f;
        #pragma unroll
        for (int cch = 0; cch < 16; cch++) {
            float4 v = *(const float4*)&row[cch * 4];
            s += v.x * v.x + v.y * v.y + v.z * v.z + v.w * v.w;
        }
        float inv = 1.0f / fmaxf(sqrtf(s), 1e-12f);
        if (tid < 32) s_qn[tid] = inv; else s_kn[tid - 32] = inv;
    }
    __syncthreads();

    // gram: 4x4 block per thread (8 qg x 8 kg), K=64 via f32x2
    const int qg = tid >> 3, kg = tid & 7;
    const int qr = qg * 4, kr = kg * 4;
    float gv[4][4];
    {
        ull acc[4][4] = {};
        #pragma unroll 4
        for (int lc = 0; lc < 16; lc++) {
            int qp = ((lc + qg) & 15) * 4;
            int kp = ((lc + kg) & 15) * 4;
            ulonglong2 qa[4], kb[4];
            #pragma unroll
            for (int i = 0; i < 4; i++)
                qa[i] = *(const ulonglong2*)&s_q[(qr + i) * 68 + qp];
            #pragma unroll
            for (int j = 0; j < 4; j++)
                kb[j] = *(const ulonglong2*)&s_k[(kr + j) * 68 + kp];
            #pragma unroll
            for (int i = 0; i < 4; i++)
                #pragma unroll
                for (int j = 0; j < 4; j++) {
                    fma2(acc[i][j], qa[i].x, kb[j].x);
                    fma2(acc[i][j], qa[i].y, kb[j].y);
                }
        }
        const float tmp = __ldg(&temp[head]);
        #pragma unroll
        for (int i = 0; i < 4; i++)
            #pragma unroll
            for (int j = 0; j < 4; j++) {
                float2 pr = unpack2(acc[i][j]);
                gv[i][j] = fmaxf((pr.x + pr.y) * s_qn[qr + i] * s_kn[kr + j] * tmp, 0.f);
            }
    }
    __syncthreads();
    float* s_g = s_q;                // overlay: G^T as s_g[d][c], stride 36
    #pragma unroll
    for (int j = 0; j < 4; j++)
        *(float4*)&s_g[(kr + j) * 36 + qr] =
            make_float4(gv[0][j], gv[1][j], gv[2][j], gv[3][j]);
    __syncthreads();

    // AV: out[c][n] = sum_d G[c][d] v[d][n]; v straight from g_dw (8B loads)
    {
        const int cog = tid >> 3, pxg = tid & 7;
        const int co = cog * 4;
        const float* vbase = g_dw + (size_t)(192 + head * 32) * HWP
                           + (r0 + pxg) * WW + cc0;
        ull av[4][4] = {};
        #pragma unroll 4
        for (int d = 0; d < 32; d++) {
            float4 g4 = *(const float4*)&s_g[d * 36 + co];
            ull gp[4] = {pack2(g4.x), pack2(g4.y), pack2(g4.z), pack2(g4.w)};
            const ull* vr = (const ull*)(vbase + (size_t)d * HWP);
            ull v0 = vr[0], v1 = vr[1], v2 = vr[2], v3 = vr[3];
            #pragma unroll
            for (int i = 0; i < 4; i++) {
                fma2(av[i][0], gp[i], v0);
                fma2(av[i][1], gp[i], v1);
                fma2(av[i][2], gp[i], v2);
                fma2(av[i][3], gp[i], v3);
            }
        }
        float* base = g_out + (t * 96 + head * 32 + co) * 4096
                    + (wy * 8 + pxg) * 64 + wx * 8;
        #pragma unroll
        for (int i = 0; i < 4; i++) {
            *(float4*)(base + i * 4096)     = cat2(av[i][0], av[i][1]);
            *(float4*)(base + i * 4096 + 4) = cat2(av[i][2], av[i][3]);
        }
    }
}

// --------------------------------------------------------------------------
// K4: out = proj_w @ (gathered tile avg), f32x2, (+4,+4) unshift on store.
// (R6 fused form — the split merge+proj regressed.)
// --------------------------------------------------------------------------
__global__ __launch_bounds__(192) void proj_gemm_kernel(float* __restrict__ out)
{
    __shared__ float sWT[C * C];
    __shared__ float sX[KC * 128];
    __shared__ int   s_toff[128 * 4];
    __shared__ int   s_dst[128];
    __shared__ float s_icnt[128];

    const int tid = threadIdx.x;
    const int p0  = blockIdx.x * 128;

    if (tid < 128) {
        int p = p0 + tid; if (p >= HWP) p = HWP - 1;
        int h = p / WW, ww = p % WW;
        int hd = h + SHIFT; if (hd >= HH) hd -= HH;
        int wd = ww + SHIFT; if (wd >= WW) wd -= WW;
        s_dst[tid] = hd * WW + wd;
        int rt[2], ct[2], nr = 0, nc = 0;
        #pragma unroll
        for (int o = 0; o < 5; o++) {
            int off = c_off[o];
            if (off <= h  && h  < off + 64) rt[nr++] = o;
            if (off <= ww && ww < off + 64) ct[nc++] = o;
        }
        #pragma unroll
        for (int m = 0; m < 4; m++) s_toff[tid * 4 + m] = -1;
        int m = 0;
        for (int a = 0; a < nr; a++)
            for (int b = 0; b < nc; b++) {
                int tt = rt[a] * 5 + ct[b];
                s_toff[tid * 4 + m++] = tt * (96 * 4096)
                    + (h - c_off[rt[a]]) * 64 + (ww - c_off[ct[b]]);
            }
        s_icnt[tid] = 1.0f / (float)(nr * nc);
    }
    for (int i = tid; i < C * C; i += 192) sWT[i] = g_pwT[i];

    const int og = tid / 16, pg = tid % 16;
    ull acc[8][4] = {};

    for (int kc = 0; kc < C / KC; kc++) {
        __syncthreads();
        for (int i = tid; i < KC * 128; i += 192) {
            int k = i >> 7, px = i & 127;
            int cch = (kc * KC + k) * 4096;
            float s = 0.f;
            #pragma unroll
            for (int m = 0; m < 4; m++) {
                int off = s_toff[px * 4 + m];
                if (off >= 0) s += g_out[off + cch];
            }
            sX[k * 128 + px] = s * s_icnt[px];
        }
        __syncthreads();
        #pragma unroll
        for (int k = 0; k < KC; k++) {
            float4 wa = *(const float4*)&sWT[(kc * KC + k) * C + og * 8];
            float4 wb = *(const float4*)&sWT[(kc * KC + k) * C + og * 8 + 4];
            ull wp[8];
            wp[0] = pack2(wa.x); wp[1] = pack2(wa.y);
            wp[2] = pack2(wa.z); wp[3] = pack2(wa.w);
            wp[4] = pack2(wb.x); wp[5] = pack2(wb.y);
            wp[6] = pack2(wb.z); wp[7] = pack2(wb.w);
            ulonglong2 xa = *(const ulonglong2*)&sX[k * 128 + pg * 8];
            ulonglong2 xb = *(const ulonglong2*)&sX[k * 128 + pg * 8 + 4];
            #pragma unroll
            for (int o = 0; o < 8; o++) {
                fma2(acc[o][0], wp[o], xa.x);
                fma2(acc[o][1], wp[o], xa.y);
                fma2(acc[o][2], wp[o], xb.x);
                fma2(acc[o][3], wp[o], xb.y);
            }
        }
    }
    if (p0 + pg * 8 < HWP) {
        #pragma unroll
        for (int o = 0; o < 8; o++) {
            const int oc = og * 8 + o;
            float4 v0 = cat2(acc[o][0], acc[o][1]);
            float4 v1 = cat2(acc[o][2], acc[o][3]);
            float vv[8] = {v0.x, v0.y, v0.z, v0.w, v1.x, v1.y, v1.z, v1.w};
            #pragma unroll
            for (int j = 0; j < 8; j++)
                out[oc * HWP + s_dst[pg * 8 + j]] = vv[j];
        }
    }
}

// --------------------------------------------------------------------------
extern "C" void kernel_launch(void* const* d_in, const int* in_sizes, int n_in,
                              void* d_out, int out_size)
{
    const float* x    = (const float*)d_in[0];   // (1,96,264,264)
    const float* temp = (const float*)d_in[1];   // (3,1,1)
    const float* qkvw = (const float*)d_in[2];   // (288,96)
    const float* dww  = (const float*)d_in[3];   // (288,1,3,3)
    const float* pw   = (const float*)d_in[4];   // (96,96)
    float* out = (float*)d_out;                  // (1,96,264,264)

    transpose_w_kernel<<<(C3 * C + 255) / 256, 256>>>(qkvw, pw);
    qkv_gemm_kernel<<<dim3((HWP + 127) / 128, 3), 192>>>(x);
    dwconv_kernel<<<dim3((HWP / 8 + 255) / 256, C3), 256>>>(dww);
    attn_kernel<<<dim3(1600, 3), 64>>>(temp);
    proj_gemm_kernel<<<(HWP + 127) / 128, 192>>>(out);
}

// round 12
// speedup vs baseline: 1.3051x; 1.1168x over previous
#include <cuda_runtime.h>
#include <cstdint>

#define HH 264
#define WW 264
#define HWP (HH*WW)      // 69696
#define C 96
#define C3 288
#define SHIFT 4

typedef unsigned long long ull;

// ---- scratch (static device globals; allocation is forbidden) ----
__device__ float g_qkv[C3 * HWP];        // after 1x1 conv (shifted frame)
__device__ float g_dw [C3 * HWP];        // after depthwise 3x3
__device__ float g_out[25 * C * 4096];   // per-tile attention output
__device__ float g_wT [C * C3];          // qkv_w transposed [k][oc]
__device__ float g_pwT[C * C];           // proj_w transposed [k][oc]

__constant__ int c_off[5] = {0, 50, 100, 150, 200};

// ---- packed fp32x2 helpers (Blackwell FFMA2: PTX-only) ----
__device__ __forceinline__ ull pack2(float x) {
    unsigned int u = __float_as_uint(x);
    ull r;
    asm("mov.b64 %0, {%1, %1};" : "=l"(r) : "r"(u));
    return r;
}
__device__ __forceinline__ void fma2(ull& d, ull a, ull b) {
    asm("fma.rn.f32x2 %0, %1, %2, %0;" : "+l"(d) : "l"(a), "l"(b));
}
__device__ __forceinline__ float2 unpack2(ull v) {
    unsigned int lo, hi;
    asm("mov.b64 {%0, %1}, %2;" : "=r"(lo), "=r"(hi) : "l"(v));
    return make_float2(__uint_as_float(lo), __uint_as_float(hi));
}
__device__ __forceinline__ float4 cat2(ull a, ull b) {
    float2 x = unpack2(a), y = unpack2(b);
    return make_float4(x.x, x.y, y.x, y.y);
}

// ---- tf32 split helper (3xTF32 trick) ----
__device__ __forceinline__ void tf32_split(float v, float& hi, float& lo) {
    uint32_t hb;
    asm("cvt.rna.tf32.f32 %0, %1;" : "=r"(hb) : "f"(v));
    hi = __uint_as_float(hb);
    float r = v - hi;
    uint32_t lb;
    asm("cvt.rna.tf32.f32 %0, %1;" : "=r"(lb) : "f"(r));
    lo = __uint_as_float(lb);
}

#define MMA_TF32(c, a, b0, b1) \
    asm volatile("mma.sync.aligned.m16n8k8.row.col.f32.tf32.tf32.f32 " \
        "{%0,%1,%2,%3}, {%4,%5,%6,%7}, {%8,%9}, {%0,%1,%2,%3};" \
        : "+f"((c)[0]), "+f"((c)[1]), "+f"((c)[2]), "+f"((c)[3]) \
        : "r"((a)[0]), "r"((a)[1]), "r"((a)[2]), "r"((a)[3]), \
          "r"(b0), "r"(b1))

// --------------------------------------------------------------------------
// K0: transpose the two weight matrices once (tiny)
// --------------------------------------------------------------------------
__global__ void transpose_w_kernel(const float* __restrict__ qkvw,
                                   const float* __restrict__ pw)
{
    int i = blockIdx.x * 256 + threadIdx.x;
    if (i < C3 * C) { int oc = i / C, k = i % C; g_wT [k * C3 + oc] = qkvw[i]; }
    if (i < C  * C) { int oc = i / C, k = i % C; g_pwT[k * C  + oc] = pw[i]; }
}

// --------------------------------------------------------------------------
// K1: qkv = qkv_w @ x_shifted via mma.sync tf32 (3xTF32 = fp32 accuracy).
// Block: M=128 px, N=96 oc (blockIdx.y selects the oc group), K=96.
// 256 threads = 8 warps in a 4x2 (m,n) grid; warp = 2 m-tiles x 6 n-tiles
// of m16n8k8. A/B split hi+lo in smem; D = Ah*Bh + Al*Bh + Ah*Bl.
// smem strides 136/104 words (=8 mod 32) -> conflict-free fragment loads.
// --------------------------------------------------------------------------
#define XS 136
#define WS2 104
__global__ __launch_bounds__(256, 2) void qkv_mma_kernel(const float* __restrict__ x)
{
    __shared__ float sXhi[16 * XS], sXlo[16 * XS];
    __shared__ float sWhi[16 * WS2], sWlo[16 * WS2];
    __shared__ int   s_src[128];

    const int tid  = threadIdx.x;
    const int p0   = blockIdx.x * 128;
    const int oc0  = blockIdx.y * C;
    const int lane = tid & 31, wid = tid >> 5;
    const int g    = lane >> 2, t4 = lane & 3;
    const int px0  = (wid & 3) * 32;
    const int n0   = (wid >> 2) * 48;

    if (tid < 128) {
        int p = p0 + tid; if (p >= HWP) p = HWP - 1;
        int h = p / WW, ww = p % WW;
        int hs = h + SHIFT; if (hs >= HH) hs -= HH;
        int ws = ww + SHIFT; if (ws >= WW) ws -= WW;
        s_src[tid] = hs * WW + ws;
    }
    __syncthreads();

    float pfX[8], pfW[6];
    #pragma unroll
    for (int j = 0; j < 8; j++) {
        int idx = tid + j * 256;
        pfX[j] = x[(idx >> 7) * HWP + s_src[idx & 127]];
    }
    #pragma unroll
    for (int j = 0; j < 6; j++) {
        int idx = tid + j * 256;
        pfW[j] = g_wT[(idx / 96) * C3 + oc0 + idx % 96];
    }

    float acc[2][6][4] = {};

    for (int kc = 0; kc < 6; kc++) {
        __syncthreads();
        #pragma unroll
        for (int j = 0; j < 8; j++) {
            int idx = tid + j * 256;
            int k = idx >> 7, px = idx & 127;
            float hi, lo;
            tf32_split(pfX[j], hi, lo);
            sXhi[k * XS + px] = hi;
            sXlo[k * XS + px] = lo;
        }
        #pragma unroll
        for (int j = 0; j < 6; j++) {
            int idx = tid + j * 256;
            int k = idx / 96, oc = idx % 96;
            float hi, lo;
            tf32_split(pfW[j], hi, lo);
            sWhi[k * WS2 + oc] = hi;
            sWlo[k * WS2 + oc] = lo;
        }
        __syncthreads();
        if (kc < 5) {
            #pragma unroll
            for (int j = 0; j < 8; j++) {
                int idx = tid + j * 256;
                pfX[j] = x[((kc + 1) * 16 + (idx >> 7)) * HWP + s_src[idx & 127]];
            }
            #pragma unroll
            for (int j = 0; j < 6; j++) {
                int idx = tid + j * 256;
                pfW[j] = g_wT[((kc + 1) * 16 + idx / 96) * C3 + oc0 + idx % 96];
            }
        }
        #pragma unroll
        for (int ks = 0; ks < 2; ks++) {
            const int kA = (ks * 8 + t4) * XS;
            const int kB = (ks * 8 + t4 + 4) * XS;
            const int kAw = (ks * 8 + t4) * WS2;
            const int kBw = (ks * 8 + t4 + 4) * WS2;
            uint32_t ah[2][4], al[2][4];
            #pragma unroll
            for (int tm = 0; tm < 2; tm++) {
                int pxb = px0 + 16 * tm + g;
                ah[tm][0] = __float_as_uint(sXhi[kA + pxb]);
                ah[tm][1] = __float_as_uint(sXhi[kA + pxb + 8]);
                ah[tm][2] = __float_as_uint(sXhi[kB + pxb]);
                ah[tm][3] = __float_as_uint(sXhi[kB + pxb + 8]);
                al[tm][0] = __float_as_uint(sXlo[kA + pxb]);
                al[tm][1] = __float_as_uint(sXlo[kA + pxb + 8]);
                al[tm][2] = __float_as_uint(sXlo[kB + pxb]);
                al[tm][3] = __float_as_uint(sXlo[kB + pxb + 8]);
            }
            #pragma unroll
            for (int tn = 0; tn < 6; tn++) {
                int nb = n0 + 8 * tn + g;
                uint32_t bh0 = __float_as_uint(sWhi[kAw + nb]);
                uint32_t bh1 = __float_as_uint(sWhi[kBw + nb]);
                uint32_t bl0 = __float_as_uint(sWlo[kAw + nb]);
                uint32_t bl1 = __float_as_uint(sWlo[kBw + nb]);
                #pragma unroll
                for (int tm = 0; tm < 2; tm++) {
                    MMA_TF32(acc[tm][tn], ah[tm], bh0, bh1);
                    MMA_TF32(acc[tm][tn], al[tm], bh0, bh1);
                    MMA_TF32(acc[tm][tn], ah[tm], bl0, bl1);
                }
            }
        }
    }

    // epilogue: c0/c1 -> (px, n), (px, n+1); c2/c3 -> (px+8, n), (px+8, n+1)
    #pragma unroll
    for (int tm = 0; tm < 2; tm++) {
        int pA = p0 + px0 + 16 * tm + g;
        int pB = pA + 8;
        #pragma unroll
        for (int tn = 0; tn < 6; tn++) {
            int n = oc0 + n0 + 8 * tn + 2 * t4;
            float* c = acc[tm][tn];
            if (pA < HWP) {
                g_qkv[n * HWP + pA]       = c[0];
                g_qkv[(n + 1) * HWP + pA] = c[1];
            }
            if (pB < HWP) {
                g_qkv[n * HWP + pB]       = c[2];
                g_qkv[(n + 1) * HWP + pB] = c[3];
            }
        }
    }
}

// --------------------------------------------------------------------------
// K2: depthwise 3x3, pad 1, 288 channels, 8 px per thread (264 = 33*8).
// --------------------------------------------------------------------------
__global__ __launch_bounds__(256) void dwconv_kernel(const float* __restrict__ dww)
{
    const int c = blockIdx.y;
    const int g = blockIdx.x * 256 + threadIdx.x;
    if (g >= HWP / 8) return;
    const int h  = g / 33;
    const int w0 = (g % 33) * 8;
    const float* in = g_qkv + c * HWP;

    float wt[9];
    #pragma unroll
    for (int i = 0; i < 9; i++) wt[i] = __ldg(&dww[c * 9 + i]);

    float o[8] = {};
    #pragma unroll
    for (int ky = 0; ky < 3; ky++) {
        int y = h + ky - 1;
        if ((unsigned)y >= HH) continue;
        const float* b = in + y * WW + w0;
        float4 A = *(const float4*)b;
        float4 B = *(const float4*)(b + 4);
        float L = (w0 > 0) ? __ldg(b - 1) : 0.f;
        float R = (w0 + 8 < WW) ? __ldg(b + 8) : 0.f;
        float v[10] = {L, A.x, A.y, A.z, A.w, B.x, B.y, B.z, B.w, R};
        #pragma unroll
        for (int kx = 0; kx < 3; kx++) {
            float wv = wt[ky * 3 + kx];
            #pragma unroll
            for (int pp = 0; pp < 8; pp++) o[pp] += wv * v[kx + pp];
        }
    }
    float* dst = g_dw + c * HWP + h * WW + w0;
    *(float4*)dst       = make_float4(o[0], o[1], o[2], o[3]);
    *(float4*)(dst + 4) = make_float4(o[4], o[5], o[6], o[7]);
}

// --------------------------------------------------------------------------
// K3: per-(window,head) channel attention. grid (1600,3), 64 threads.
// R5 form: direct-LDG v in AV, launch_bounds(64,10).
// --------------------------------------------------------------------------
__global__ __launch_bounds__(64, 10) void attn_kernel(const float* __restrict__ temp)
{
    __shared__ float s_q[32 * 68];   // swizzled; reused as s_g (32*36) after gram
    __shared__ float s_k[32 * 68];   // swizzled
    __shared__ float s_qn[32], s_kn[32];

    const int tid  = threadIdx.x;
    const int win  = blockIdx.x;
    const int head = blockIdx.y;
    const int t    = win >> 6;
    const int w64  = win & 63;
    const int wy = w64 >> 3, wx = w64 & 7;
    const int r0  = c_off[t / 5] + wy * 8;
    const int cc0 = c_off[t % 5] + wx * 8;

    for (int i = tid; i < 64 * 32; i += 64) {
        int ch = i >> 5, pr = i & 31;
        int r = pr >> 2, j = (pr & 3) * 2;
        int gch = (ch < 32) ? head * 32 + ch : 96 + head * 32 + (ch - 32);
        float2 v = *(const float2*)&g_dw[gch * HWP + (r0 + r) * WW + cc0 + j];
        int n = r * 8 + j;
        int row = ch & 31;
        float* dst = (ch < 32) ? s_q : s_k;
        int phys = (((n >> 2) + (row >> 2)) & 15) * 4 + (n & 3);
        *(float2*)&dst[row * 68 + phys] = v;
    }
    __syncthreads();

    {
        const float* row = (tid < 32) ? (s_q + tid * 68) : (s_k + (tid - 32) * 68);
        float s = 0.f;
        #pragma unroll
        for (int cch = 0; cch < 16; cch++) {
            float4 v = *(const float4*)&row[cch * 4];
            s += v.x * v.x + v.y * v.y + v.z * v.z + v.w * v.w;
        }
        float inv = 1.0f / fmaxf(sqrtf(s), 1e-12f);
        if (tid < 32) s_qn[tid] = inv; else s_kn[tid - 32] = inv;
    }
    __syncthreads();

    const int qg = tid >> 3, kg = tid & 7;
    const int qr = qg * 4, kr = kg * 4;
    float gv[4][4];
    {
        ull acc[4][4] = {};
        #pragma unroll 4
        for (int lc = 0; lc < 16; lc++) {
            int qp = ((lc + qg) & 15) * 4;
            int kp = ((lc + kg) & 15) * 4;
            ulonglong2 qa[4], kb[4];
            #pragma unroll
            for (int i = 0; i < 4; i++)
                qa[i] = *(const ulonglong2*)&s_q[(qr + i) * 68 + qp];
            #pragma unroll
            for (int j = 0; j < 4; j++)
                kb[j] = *(const ulonglong2*)&s_k[(kr + j) * 68 + kp];
            #pragma unroll
            for (int i = 0; i < 4; i++)
                #pragma unroll
                for (int j = 0; j < 4; j++) {
                    fma2(acc[i][j], qa[i].x, kb[j].x);
                    fma2(acc[i][j], qa[i].y, kb[j].y);
                }
        }
        const float tmp = __ldg(&temp[head]);
        #pragma unroll
        for (int i = 0; i < 4; i++)
            #pragma unroll
            for (int j = 0; j < 4; j++) {
                float2 pr = unpack2(acc[i][j]);
                gv[i][j] = fmaxf((pr.x + pr.y) * s_qn[qr + i] * s_kn[kr + j] * tmp, 0.f);
            }
    }
    __syncthreads();
    float* s_g = s_q;
    #pragma unroll
    for (int j = 0; j < 4; j++)
        *(float4*)&s_g[(kr + j) * 36 + qr] =
            make_float4(gv[0][j], gv[1][j], gv[2][j], gv[3][j]);
    __syncthreads();

    {
        const int cog = tid >> 3, pxg = tid & 7;
        const int co = cog * 4;
        const float* vbase = g_dw + (size_t)(192 + head * 32) * HWP
                           + (r0 + pxg) * WW + cc0;
        ull av[4][4] = {};
        #pragma unroll 4
        for (int d = 0; d < 32; d++) {
            float4 g4 = *(const float4*)&s_g[d * 36 + co];
            ull gp[4] = {pack2(g4.x), pack2(g4.y), pack2(g4.z), pack2(g4.w)};
            const ull* vr = (const ull*)(vbase + (size_t)d * HWP);
            ull v0 = vr[0], v1 = vr[1], v2 = vr[2], v3 = vr[3];
            #pragma unroll
            for (int i = 0; i < 4; i++) {
                fma2(av[i][0], gp[i], v0);
                fma2(av[i][1], gp[i], v1);
                fma2(av[i][2], gp[i], v2);
                fma2(av[i][3], gp[i], v3);
            }
        }
        float* base = g_out + (t * 96 + head * 32 + co) * 4096
                    + (wy * 8 + pxg) * 64 + wx * 8;
        #pragma unroll
        for (int i = 0; i < 4; i++) {
            *(float4*)(base + i * 4096)     = cat2(av[i][0], av[i][1]);
            *(float4*)(base + i * 4096 + 4) = cat2(av[i][2], av[i][3]);
        }
    }
}

// --------------------------------------------------------------------------
// K4: out = proj_w @ (gathered tile avg), f32x2, (+4,+4) unshift on store.
// --------------------------------------------------------------------------
#define KC 16
__global__ __launch_bounds__(192) void proj_gemm_kernel(float* __restrict__ out)
{
    __shared__ float sWT[C * C];
    __shared__ float sX[KC * 128];
    __shared__ int   s_toff[128 * 4];
    __shared__ int   s_dst[128];
    __shared__ float s_icnt[128];

    const int tid = threadIdx.x;
    const int p0  = blockIdx.x * 128;

    if (tid < 128) {
        int p = p0 + tid; if (p >= HWP) p = HWP - 1;
        int h = p / WW, ww = p % WW;
        int hd = h + SHIFT; if (hd >= HH) hd -= HH;
        int wd = ww + SHIFT; if (wd >= WW) wd -= WW;
        s_dst[tid] = hd * WW + wd;
        int rt[2], ct[2], nr = 0, nc = 0;
        #pragma unroll
        for (int o = 0; o < 5; o++) {
            int off = c_off[o];
            if (off <= h  && h  < off + 64) rt[nr++] = o;
            if (off <= ww && ww < off + 64) ct[nc++] = o;
        }
        #pragma unroll
        for (int m = 0; m < 4; m++) s_toff[tid * 4 + m] = -1;
        int m = 0;
        for (int a = 0; a < nr; a++)
            for (int b = 0; b < nc; b++) {
                int tt = rt[a] * 5 + ct[b];
                s_toff[tid * 4 + m++] = tt * (96 * 4096)
                    + (h - c_off[rt[a]]) * 64 + (ww - c_off[ct[b]]);
            }
        s_icnt[tid] = 1.0f / (float)(nr * nc);
    }
    for (int i = tid; i < C * C; i += 192) sWT[i] = g_pwT[i];

    const int og = tid / 16, pg = tid % 16;
    ull acc[8][4] = {};

    for (int kc = 0; kc < C / KC; kc++) {
        __syncthreads();
        for (int i = tid; i < KC * 128; i += 192) {
            int k = i >> 7, px = i & 127;
            int cch = (kc * KC + k) * 4096;
            float s = 0.f;
            #pragma unroll
            for (int m = 0; m < 4; m++) {
                int off = s_toff[px * 4 + m];
                if (off >= 0) s += g_out[off + cch];
            }
            sX[k * 128 + px] = s * s_icnt[px];
        }
        __syncthreads();
        #pragma unroll
        for (int k = 0; k < KC; k++) {
            float4 wa = *(const float4*)&sWT[(kc * KC + k) * C + og * 8];
            float4 wb = *(const float4*)&sWT[(kc * KC + k) * C + og * 8 + 4];
            ull wp[8];
            wp[0] = pack2(wa.x); wp[1] = pack2(wa.y);
            wp[2] = pack2(wa.z); wp[3] = pack2(wa.w);
            wp[4] = pack2(wb.x); wp[5] = pack2(wb.y);
            wp[6] = pack2(wb.z); wp[7] = pack2(wb.w);
            ulonglong2 xa = *(const ulonglong2*)&sX[k * 128 + pg * 8];
            ulonglong2 xb = *(const ulonglong2*)&sX[k * 128 + pg * 8 + 4];
            #pragma unroll
            for (int o = 0; o < 8; o++) {
                fma2(acc[o][0], wp[o], xa.x);
                fma2(acc[o][1], wp[o], xa.y);
                fma2(acc[o][2], wp[o], xb.x);
                fma2(acc[o][3], wp[o], xb.y);
            }
        }
    }
    if (p0 + pg * 8 < HWP) {
        #pragma unroll
        for (int o = 0; o < 8; o++) {
            const int oc = og * 8 + o;
            float4 v0 = cat2(acc[o][0], acc[o][1]);
            float4 v1 = cat2(acc[o][2], acc[o][3]);
            float vv[8] = {v0.x, v0.y, v0.z, v0.w, v1.x, v1.y, v1.z, v1.w};
            #pragma unroll
            for (int j = 0; j < 8; j++)
                out[oc * HWP + s_dst[pg * 8 + j]] = vv[j];
        }
    }
}

// --------------------------------------------------------------------------
extern "C" void kernel_launch(void* const* d_in, const int* in_sizes, int n_in,
                              void* d_out, int out_size)
{
    const float* x    = (const float*)d_in[0];   // (1,96,264,264)
    const float* temp = (const float*)d_in[1];   // (3,1,1)
    const float* qkvw = (const float*)d_in[2];   // (288,96)
    const float* dww  = (const float*)d_in[3];   // (288,1,3,3)
    const float* pw   = (const float*)d_in[4];   // (96,96)
    float* out = (float*)d_out;                  // (1,96,264,264)

    transpose_w_kernel<<<(C3 * C + 255) / 256, 256>>>(qkvw, pw);
    qkv_mma_kernel<<<dim3((HWP + 127) / 128, 3), 256>>>(x);
    dwconv_kernel<<<dim3((HWP / 8 + 255) / 256, C3), 256>>>(dww);
    attn_kernel<<<dim3(1600, 3), 64>>>(temp);
    proj_gemm_kernel<<<(HWP + 127) / 128, 192>>>(out);
}

// round 14
// speedup vs baseline: 1.6076x; 1.2317x over previous
#include <cuda_runtime.h>
#include <cstdint>

#define HH 264
#define WW 264
#define HWP (HH*WW)      // 69696
#define C 96
#define C3 288
#define SHIFT 4

typedef unsigned long long ull;

// ---- scratch (static device globals; allocation is forbidden) ----
__device__ float g_qkv[C3 * HWP];        // after 1x1 conv (shifted frame)
__device__ float g_dw [C3 * HWP];        // after depthwise 3x3
__device__ float g_out[25 * C * 4096];   // per-tile attention output
__device__ float g_wT [C * C3];          // qkv_w transposed [k][oc]
__device__ float g_pwT[C * C];           // proj_w transposed [k][oc]

__constant__ int c_off[5] = {0, 50, 100, 150, 200};

// ---- packed fp32x2 helpers (Blackwell FFMA2: PTX-only) ----
__device__ __forceinline__ ull pack2(float x) {
    unsigned int u = __float_as_uint(x);
    ull r;
    asm("mov.b64 %0, {%1, %1};" : "=l"(r) : "r"(u));
    return r;
}
__device__ __forceinline__ void fma2(ull& d, ull a, ull b) {
    asm("fma.rn.f32x2 %0, %1, %2, %0;" : "+l"(d) : "l"(a), "l"(b));
}
__device__ __forceinline__ float2 unpack2(ull v) {
    unsigned int lo, hi;
    asm("mov.b64 {%0, %1}, %2;" : "=r"(lo), "=r"(hi) : "l"(v));
    return make_float2(__uint_as_float(lo), __uint_as_float(hi));
}
__device__ __forceinline__ float4 cat2(ull a, ull b) {
    float2 x = unpack2(a), y = unpack2(b);
    return make_float4(x.x, x.y, y.x, y.y);
}

// ---- tf32 split helper (3xTF32 trick) ----
__device__ __forceinline__ void tf32_split(float v, float& hi, float& lo) {
    uint32_t hb;
    asm("cvt.rna.tf32.f32 %0, %1;" : "=r"(hb) : "f"(v));
    hi = __uint_as_float(hb);
    float r = v - hi;
    uint32_t lb;
    asm("cvt.rna.tf32.f32 %0, %1;" : "=r"(lb) : "f"(r));
    lo = __uint_as_float(lb);
}

#define MMA_TF32(c, a, b0, b1) \
    asm volatile("mma.sync.aligned.m16n8k8.row.col.f32.tf32.tf32.f32 " \
        "{%0,%1,%2,%3}, {%4,%5,%6,%7}, {%8,%9}, {%0,%1,%2,%3};" \
        : "+f"((c)[0]), "+f"((c)[1]), "+f"((c)[2]), "+f"((c)[3]) \
        : "r"((a)[0]), "r"((a)[1]), "r"((a)[2]), "r"((a)[3]), \
          "r"(b0), "r"(b1))

// --------------------------------------------------------------------------
// K0: transpose the two weight matrices once (tiny)
// --------------------------------------------------------------------------
__global__ void transpose_w_kernel(const float* __restrict__ qkvw,
                                   const float* __restrict__ pw)
{
    int i = blockIdx.x * 256 + threadIdx.x;
    if (i < C3 * C) { int oc = i / C, k = i % C; g_wT [k * C3 + oc] = qkvw[i]; }
    if (i < C  * C) { int oc = i / C, k = i % C; g_pwT[k * C  + oc] = pw[i]; }
}

// --------------------------------------------------------------------------
// K1: qkv = qkv_w @ x_shifted via mma.sync tf32 (3xTF32 = fp32 accuracy).
// --------------------------------------------------------------------------
#define XS 136
#define WS2 104
__global__ __launch_bounds__(256, 2) void qkv_mma_kernel(const float* __restrict__ x)
{
    __shared__ float sXhi[16 * XS], sXlo[16 * XS];
    __shared__ float sWhi[16 * WS2], sWlo[16 * WS2];
    __shared__ int   s_src[128];

    const int tid  = threadIdx.x;
    const int p0   = blockIdx.x * 128;
    const int oc0  = blockIdx.y * C;
    const int lane = tid & 31, wid = tid >> 5;
    const int g    = lane >> 2, t4 = lane & 3;
    const int px0  = (wid & 3) * 32;
    const int n0   = (wid >> 2) * 48;

    if (tid < 128) {
        int p = p0 + tid; if (p >= HWP) p = HWP - 1;
        int h = p / WW, ww = p % WW;
        int hs = h + SHIFT; if (hs >= HH) hs -= HH;
        int ws = ww + SHIFT; if (ws >= WW) ws -= WW;
        s_src[tid] = hs * WW + ws;
    }
    __syncthreads();

    float pfX[8], pfW[6];
    #pragma unroll
    for (int j = 0; j < 8; j++) {
        int idx = tid + j * 256;
        pfX[j] = x[(idx >> 7) * HWP + s_src[idx & 127]];
    }
    #pragma unroll
    for (int j = 0; j < 6; j++) {
        int idx = tid + j * 256;
        pfW[j] = g_wT[(idx / 96) * C3 + oc0 + idx % 96];
    }

    float acc[2][6][4] = {};

    for (int kc = 0; kc < 6; kc++) {
        __syncthreads();
        #pragma unroll
        for (int j = 0; j < 8; j++) {
            int idx = tid + j * 256;
            int k = idx >> 7, px = idx & 127;
            float hi, lo;
            tf32_split(pfX[j], hi, lo);
            sXhi[k * XS + px] = hi;
            sXlo[k * XS + px] = lo;
        }
        #pragma unroll
        for (int j = 0; j < 6; j++) {
            int idx = tid + j * 256;
            int k = idx / 96, oc = idx % 96;
            float hi, lo;
            tf32_split(pfW[j], hi, lo);
            sWhi[k * WS2 + oc] = hi;
            sWlo[k * WS2 + oc] = lo;
        }
        __syncthreads();
        if (kc < 5) {
            #pragma unroll
            for (int j = 0; j < 8; j++) {
                int idx = tid + j * 256;
                pfX[j] = x[((kc + 1) * 16 + (idx >> 7)) * HWP + s_src[idx & 127]];
            }
            #pragma unroll
            for (int j = 0; j < 6; j++) {
                int idx = tid + j * 256;
                pfW[j] = g_wT[((kc + 1) * 16 + idx / 96) * C3 + oc0 + idx % 96];
            }
        }
        #pragma unroll
        for (int ks = 0; ks < 2; ks++) {
            const int kA = (ks * 8 + t4) * XS;
            const int kB = (ks * 8 + t4 + 4) * XS;
            const int kAw = (ks * 8 + t4) * WS2;
            const int kBw = (ks * 8 + t4 + 4) * WS2;
            uint32_t ah[2][4], al[2][4];
            #pragma unroll
            for (int tm = 0; tm < 2; tm++) {
                int pxb = px0 + 16 * tm + g;
                ah[tm][0] = __float_as_uint(sXhi[kA + pxb]);
                ah[tm][1] = __float_as_uint(sXhi[kA + pxb + 8]);
                ah[tm][2] = __float_as_uint(sXhi[kB + pxb]);
                ah[tm][3] = __float_as_uint(sXhi[kB + pxb + 8]);
                al[tm][0] = __float_as_uint(sXlo[kA + pxb]);
                al[tm][1] = __float_as_uint(sXlo[kA + pxb + 8]);
                al[tm][2] = __float_as_uint(sXlo[kB + pxb]);
                al[tm][3] = __float_as_uint(sXlo[kB + pxb + 8]);
            }
            #pragma unroll
            for (int tn = 0; tn < 6; tn++) {
                int nb = n0 + 8 * tn + g;
                uint32_t bh0 = __float_as_uint(sWhi[kAw + nb]);
                uint32_t bh1 = __float_as_uint(sWhi[kBw + nb]);
                uint32_t bl0 = __float_as_uint(sWlo[kAw + nb]);
                uint32_t bl1 = __float_as_uint(sWlo[kBw + nb]);
                #pragma unroll
                for (int tm = 0; tm < 2; tm++) {
                    MMA_TF32(acc[tm][tn], ah[tm], bh0, bh1);
                    MMA_TF32(acc[tm][tn], al[tm], bh0, bh1);
                    MMA_TF32(acc[tm][tn], ah[tm], bl0, bl1);
                }
            }
        }
    }

    #pragma unroll
    for (int tm = 0; tm < 2; tm++) {
        int pA = p0 + px0 + 16 * tm + g;
        int pB = pA + 8;
        #pragma unroll
        for (int tn = 0; tn < 6; tn++) {
            int n = oc0 + n0 + 8 * tn + 2 * t4;
            float* c = acc[tm][tn];
            if (pA < HWP) {
                g_qkv[n * HWP + pA]       = c[0];
                g_qkv[(n + 1) * HWP + pA] = c[1];
            }
            if (pB < HWP) {
                g_qkv[n * HWP + pB]       = c[2];
                g_qkv[(n + 1) * HWP + pB] = c[3];
            }
        }
    }
}

// --------------------------------------------------------------------------
// K2: depthwise 3x3, pad 1, 288 channels, 8 px per thread (264 = 33*8).
// --------------------------------------------------------------------------
__global__ __launch_bounds__(256) void dwconv_kernel(const float* __restrict__ dww)
{
    const int c = blockIdx.y;
    const int g = blockIdx.x * 256 + threadIdx.x;
    if (g >= HWP / 8) return;
    const int h  = g / 33;
    const int w0 = (g % 33) * 8;
    const float* in = g_qkv + c * HWP;

    float wt[9];
    #pragma unroll
    for (int i = 0; i < 9; i++) wt[i] = __ldg(&dww[c * 9 + i]);

    float o[8] = {};
    #pragma unroll
    for (int ky = 0; ky < 3; ky++) {
        int y = h + ky - 1;
        if ((unsigned)y >= HH) continue;
        const float* b = in + y * WW + w0;
        float4 A = *(const float4*)b;
        float4 B = *(const float4*)(b + 4);
        float L = (w0 > 0) ? __ldg(b - 1) : 0.f;
        float R = (w0 + 8 < WW) ? __ldg(b + 8) : 0.f;
        float v[10] = {L, A.x, A.y, A.z, A.w, B.x, B.y, B.z, B.w, R};
        #pragma unroll
        for (int kx = 0; kx < 3; kx++) {
            float wv = wt[ky * 3 + kx];
            #pragma unroll
            for (int pp = 0; pp < 8; pp++) o[pp] += wv * v[kx + pp];
        }
    }
    float* dst = g_dw + c * HWP + h * WW + w0;
    *(float4*)dst       = make_float4(o[0], o[1], o[2], o[3]);
    *(float4*)(dst + 4) = make_float4(o[4], o[5], o[6], o[7]);
}

// --------------------------------------------------------------------------
// K3: per-(window,head) channel attention. grid (1600,3), 64 threads.
// --------------------------------------------------------------------------
__global__ __launch_bounds__(64, 10) void attn_kernel(const float* __restrict__ temp)
{
    __shared__ float s_q[32 * 68];
    __shared__ float s_k[32 * 68];
    __shared__ float s_qn[32], s_kn[32];

    const int tid  = threadIdx.x;
    const int win  = blockIdx.x;
    const int head = blockIdx.y;
    const int t    = win >> 6;
    const int w64  = win & 63;
    const int wy = w64 >> 3, wx = w64 & 7;
    const int r0  = c_off[t / 5] + wy * 8;
    const int cc0 = c_off[t % 5] + wx * 8;

    for (int i = tid; i < 64 * 32; i += 64) {
        int ch = i >> 5, pr = i & 31;
        int r = pr >> 2, j = (pr & 3) * 2;
        int gch = (ch < 32) ? head * 32 + ch : 96 + head * 32 + (ch - 32);
        float2 v = *(const float2*)&g_dw[gch * HWP + (r0 + r) * WW + cc0 + j];
        int n = r * 8 + j;
        int row = ch & 31;
        float* dst = (ch < 32) ? s_q : s_k;
        int phys = (((n >> 2) + (row >> 2)) & 15) * 4 + (n & 3);
        *(float2*)&dst[row * 68 + phys] = v;
    }
    __syncthreads();

    {
        const float* row = (tid < 32) ? (s_q + tid * 68) : (s_k + (tid - 32) * 68);
        float s = 0.f;
        #pragma unroll
        for (int cch = 0; cch < 16; cch++) {
            float4 v = *(const float4*)&row[cch * 4];
            s += v.x * v.x + v.y * v.y + v.z * v.z + v.w * v.w;
        }
        float inv = 1.0f / fmaxf(sqrtf(s), 1e-12f);
        if (tid < 32) s_qn[tid] = inv; else s_kn[tid - 32] = inv;
    }
    __syncthreads();

    const int qg = tid >> 3, kg = tid & 7;
    const int qr = qg * 4, kr = kg * 4;
    float gv[4][4];
    {
        ull acc[4][4] = {};
        #pragma unroll 4
        for (int lc = 0; lc < 16; lc++) {
            int qp = ((lc + qg) & 15) * 4;
            int kp = ((lc + kg) & 15) * 4;
            ulonglong2 qa[4], kb[4];
            #pragma unroll
            for (int i = 0; i < 4; i++)
                qa[i] = *(const ulonglong2*)&s_q[(qr + i) * 68 + qp];
            #pragma unroll
            for (int j = 0; j < 4; j++)
                kb[j] = *(const ulonglong2*)&s_k[(kr + j) * 68 + kp];
            #pragma unroll
            for (int i = 0; i < 4; i++)
                #pragma unroll
                for (int j = 0; j < 4; j++) {
                    fma2(acc[i][j], qa[i].x, kb[j].x);
                    fma2(acc[i][j], qa[i].y, kb[j].y);
                }
        }
        const float tmp = __ldg(&temp[head]);
        #pragma unroll
        for (int i = 0; i < 4; i++)
            #pragma unroll
            for (int j = 0; j < 4; j++) {
                float2 pr = unpack2(acc[i][j]);
                gv[i][j] = fmaxf((pr.x + pr.y) * s_qn[qr + i] * s_kn[kr + j] * tmp, 0.f);
            }
    }
    __syncthreads();
    float* s_g = s_q;
    #pragma unroll
    for (int j = 0; j < 4; j++)
        *(float4*)&s_g[(kr + j) * 36 + qr] =
            make_float4(gv[0][j], gv[1][j], gv[2][j], gv[3][j]);
    __syncthreads();

    {
        const int cog = tid >> 3, pxg = tid & 7;
        const int co = cog * 4;
        const float* vbase = g_dw + (size_t)(192 + head * 32) * HWP
                           + (r0 + pxg) * WW + cc0;
        ull av[4][4] = {};
        #pragma unroll 4
        for (int d = 0; d < 32; d++) {
            float4 g4 = *(const float4*)&s_g[d * 36 + co];
            ull gp[4] = {pack2(g4.x), pack2(g4.y), pack2(g4.z), pack2(g4.w)};
            const ull* vr = (const ull*)(vbase + (size_t)d * HWP);
            ull v0 = vr[0], v1 = vr[1], v2 = vr[2], v3 = vr[3];
            #pragma unroll
            for (int i = 0; i < 4; i++) {
                fma2(av[i][0], gp[i], v0);
                fma2(av[i][1], gp[i], v1);
                fma2(av[i][2], gp[i], v2);
                fma2(av[i][3], gp[i], v3);
            }
        }
        float* base = g_out + (t * 96 + head * 32 + co) * 4096
                    + (wy * 8 + pxg) * 64 + wx * 8;
        #pragma unroll
        for (int i = 0; i < 4; i++) {
            *(float4*)(base + i * 4096)     = cat2(av[i][0], av[i][1]);
            *(float4*)(base + i * 4096 + 4) = cat2(av[i][2], av[i][3]);
        }
    }
}

// --------------------------------------------------------------------------
// K4: out = proj_w @ (gathered tile avg) via mma.sync tf32 (3xTF32).
// X-stage gathers <=4 overlapping tiles (pre-summed in prefetch regs),
// icnt applied at smem store, (+4,+4) unshift on epilogue.
// FIX vs R13: W tile is 16*96=1536 elems -> SIX prefetch regs, not 3.
// --------------------------------------------------------------------------
__global__ __launch_bounds__(256, 2) void proj_mma_kernel(float* __restrict__ out)
{
    __shared__ float sXhi[16 * XS], sXlo[16 * XS];
    __shared__ float sWhi[16 * WS2], sWlo[16 * WS2];
    __shared__ int   s_toff[128 * 4];
    __shared__ int   s_dst[128];
    __shared__ float s_icnt[128];

    const int tid  = threadIdx.x;
    const int p0   = blockIdx.x * 128;
    const int lane = tid & 31, wid = tid >> 5;
    const int g    = lane >> 2, t4 = lane & 3;
    const int px0  = (wid & 3) * 32;
    const int n0   = (wid >> 2) * 48;

    if (tid < 128) {
        int p = p0 + tid; if (p >= HWP) p = HWP - 1;
        int h = p / WW, ww = p % WW;
        int hd = h + SHIFT; if (hd >= HH) hd -= HH;
        int wd = ww + SHIFT; if (wd >= WW) wd -= WW;
        s_dst[tid] = hd * WW + wd;
        int rt[2], ct[2], nr = 0, nc = 0;
        #pragma unroll
        for (int o = 0; o < 5; o++) {
            int off = c_off[o];
            if (off <= h  && h  < off + 64) rt[nr++] = o;
            if (off <= ww && ww < off + 64) ct[nc++] = o;
        }
        #pragma unroll
        for (int m = 0; m < 4; m++) s_toff[tid * 4 + m] = -1;
        int m = 0;
        for (int a = 0; a < nr; a++)
            for (int b = 0; b < nc; b++) {
                int tt = rt[a] * 5 + ct[b];
                s_toff[tid * 4 + m++] = tt * (96 * 4096)
                    + (h - c_off[rt[a]]) * 64 + (ww - c_off[ct[b]]);
            }
        s_icnt[tid] = 1.0f / (float)(nr * nc);
    }
    __syncthreads();

    float pfX[8], pfW[6];
    #pragma unroll
    for (int j = 0; j < 8; j++) {
        int idx = tid + j * 256;
        int k = idx >> 7, px = idx & 127;
        int cch = k * 4096;
        float s = 0.f;
        #pragma unroll
        for (int m = 0; m < 4; m++) {
            int off = s_toff[px * 4 + m];
            if (off >= 0) s += g_out[off + cch];
        }
        pfX[j] = s;
    }
    #pragma unroll
    for (int j = 0; j < 6; j++) {
        int idx = tid + j * 256;
        pfW[j] = g_pwT[(idx / 96) * C + idx % 96];
    }

    float acc[2][6][4] = {};

    for (int kc = 0; kc < 6; kc++) {
        __syncthreads();
        #pragma unroll
        for (int j = 0; j < 8; j++) {
            int idx = tid + j * 256;
            int k = idx >> 7, px = idx & 127;
            float hi, lo;
            tf32_split(pfX[j] * s_icnt[px], hi, lo);
            sXhi[k * XS + px] = hi;
            sXlo[k * XS + px] = lo;
        }
        #pragma unroll
        for (int j = 0; j < 6; j++) {
            int idx = tid + j * 256;
            int k = idx / 96, oc = idx % 96;
            float hi, lo;
            tf32_split(pfW[j], hi, lo);
            sWhi[k * WS2 + oc] = hi;
            sWlo[k * WS2 + oc] = lo;
        }
        __syncthreads();
        if (kc < 5) {
            #pragma unroll
            for (int j = 0; j < 8; j++) {
                int idx = tid + j * 256;
                int k = idx >> 7, px = idx & 127;
                int cch = ((kc + 1) * 16 + k) * 4096;
                float s = 0.f;
                #pragma unroll
                for (int m = 0; m < 4; m++) {
                    int off = s_toff[px * 4 + m];
                    if (off >= 0) s += g_out[off + cch];
                }
                pfX[j] = s;
            }
            #pragma unroll
            for (int j = 0; j < 6; j++) {
                int idx = tid + j * 256;
                pfW[j] = g_pwT[((kc + 1) * 16 + idx / 96) * C + idx % 96];
            }
        }
        #pragma unroll
        for (int ks = 0; ks < 2; ks++) {
            const int kA = (ks * 8 + t4) * XS;
            const int kB = (ks * 8 + t4 + 4) * XS;
            const int kAw = (ks * 8 + t4) * WS2;
            const int kBw = (ks * 8 + t4 + 4) * WS2;
            uint32_t ah[2][4], al[2][4];
            #pragma unroll
            for (int tm = 0; tm < 2; tm++) {
                int pxb = px0 + 16 * tm + g;
                ah[tm][0] = __float_as_uint(sXhi[kA + pxb]);
                ah[tm][1] = __float_as_uint(sXhi[kA + pxb + 8]);
                ah[tm][2] = __float_as_uint(sXhi[kB + pxb]);
                ah[tm][3] = __float_as_uint(sXhi[kB + pxb + 8]);
                al[tm][0] = __float_as_uint(sXlo[kA + pxb]);
                al[tm][1] = __float_as_uint(sXlo[kA + pxb + 8]);
                al[tm][2] = __float_as_uint(sXlo[kB + pxb]);
                al[tm][3] = __float_as_uint(sXlo[kB + pxb + 8]);
            }
            #pragma unroll
            for (int tn = 0; tn < 6; tn++) {
                int nb = n0 + 8 * tn + g;
                uint32_t bh0 = __float_as_uint(sWhi[kAw + nb]);
                uint32_t bh1 = __float_as_uint(sWhi[kBw + nb]);
                uint32_t bl0 = __float_as_uint(sWlo[kAw + nb]);
                uint32_t bl1 = __float_as_uint(sWlo[kBw + nb]);
                #pragma unroll
                for (int tm = 0; tm < 2; tm++) {
                    MMA_TF32(acc[tm][tn], ah[tm], bh0, bh1);
                    MMA_TF32(acc[tm][tn], al[tm], bh0, bh1);
                    MMA_TF32(acc[tm][tn], ah[tm], bl0, bl1);
                }
            }
        }
    }

    // epilogue: scatter through the (+4,+4) unshift map
    #pragma unroll
    for (int tm = 0; tm < 2; tm++) {
        int lA = px0 + 16 * tm + g;
        int lB = lA + 8;
        #pragma unroll
        for (int tn = 0; tn < 6; tn++) {
            int n = n0 + 8 * tn + 2 * t4;
            float* c = acc[tm][tn];
            if (p0 + lA < HWP) {
                out[n * HWP + s_dst[lA]]       = c[0];
                out[(n + 1) * HWP + s_dst[lA]] = c[1];
            }
            if (p0 + lB < HWP) {
                out[n * HWP + s_dst[lB]]       = c[2];
                out[(n + 1) * HWP + s_dst[lB]] = c[3];
            }
        }
    }
}

// --------------------------------------------------------------------------
extern "C" void kernel_launch(void* const* d_in, const int* in_sizes, int n_in,
                              void* d_out, int out_size)
{
    const float* x    = (const float*)d_in[0];   // (1,96,264,264)
    const float* temp = (const float*)d_in[1];   // (3,1,1)
    const float* qkvw = (const float*)d_in[2];   // (288,96)
    const float* dww  = (const float*)d_in[3];   // (288,1,3,3)
    const float* pw   = (const float*)d_in[4];   // (96,96)
    float* out = (float*)d_out;                  // (1,96,264,264)

    transpose_w_kernel<<<(C3 * C + 255) / 256, 256>>>(qkvw, pw);
    qkv_mma_kernel<<<dim3((HWP + 127) / 128, 3), 256>>>(x);
    dwconv_kernel<<<dim3((HWP / 8 + 255) / 256, C3), 256>>>(dww);
    attn_kernel<<<dim3(1600, 3), 64>>>(temp);
    proj_mma_kernel<<<(HWP + 127) / 128, 256>>>(out);
}